// round 2
// baseline (speedup 1.0000x reference)
#include <cuda_runtime.h>
#include <math.h>

// ---------------------------------------------------------------------------
// DGCNN forward: 4x GCNConv(tanh) -> concat(97) -> top-30 sort pool ->
// Conv1d(1,16,97,s97) -> MaxPool(2) -> Conv1d(16,32,5) -> FC(352,128) -> FC(128,1)
// N=100000 nodes, E=1600000 edges, 1000 graphs x 100 nodes.
// ---------------------------------------------------------------------------

#define NN 100000
#define EE 1600000
#define NG 1000
#define HID 32
#define DLAT 97

// scratch (static __device__: no allocation allowed)
__device__ float g_deg[NN];
__device__ float g_dinv[NN];
__device__ float g_dinv2[NN];
__device__ float g_norm[EE];
__device__ float g_xw[NN * 32];
__device__ float g_acc[NN * 32];
__device__ float g_lat[NN * DLAT];
__device__ float g_xw4[NN];
__device__ float g_acc4[NN];

__device__ __forceinline__ void red_add_f32(float* p, float v) {
    asm volatile("red.global.add.f32 [%0], %1;" :: "l"(p), "f"(v) : "memory");
}
__device__ __forceinline__ void red_add_v4(float4* p, float x, float y, float z, float w) {
    asm volatile("red.global.add.v4.f32 [%0], {%1,%2,%3,%4};"
                 :: "l"(p), "f"(x), "f"(y), "f"(z), "f"(w) : "memory");
}

// ---- degree / normalization (layer-invariant, computed once) ---------------

__global__ void k_init_deg(int n) {
    int i = blockIdx.x * blockDim.x + threadIdx.x;
    if (i < n) g_deg[i] = 1.0f;  // self-loop weight
}

__global__ void k_edge_deg(const int* __restrict__ dst, const float* __restrict__ ew, int e) {
    int i = blockIdx.x * blockDim.x + threadIdx.x;
    if (i < e) red_add_f32(&g_deg[dst[i]], ew[i]);
}

__global__ void k_dinv(int n) {
    int i = blockIdx.x * blockDim.x + threadIdx.x;
    if (i < n) {
        float d = rsqrtf(g_deg[i]);
        g_dinv[i]  = d;
        g_dinv2[i] = d * d;
    }
}

__global__ void k_edge_norm(const int* __restrict__ src, const int* __restrict__ dst,
                            const float* __restrict__ ew, int e) {
    int i = blockIdx.x * blockDim.x + threadIdx.x;
    if (i < e) g_norm[i] = g_dinv[src[i]] * ew[i] * g_dinv[dst[i]];
}

// ---- node-side kernels: (tanh of prev acc | embedding) -> xw = h@W,
//      acc init = xw * dinv^2  (self-loop term). Warp per node. ---------------

__global__ void k_node_emb(const int* __restrict__ z, const float* __restrict__ z_emb,
                           const float* __restrict__ W, int n) {
    __shared__ float sW[1024];
    __shared__ float sH[8][32];
    int tid = threadIdx.x;
    for (int i = tid; i < 1024; i += 256) sW[i] = W[i];
    __syncthreads();
    int warp = tid >> 5, lane = tid & 31;
    int node = blockIdx.x * 8 + warp;
    if (node >= n) return;
    float h = z_emb[z[node] * 32 + lane];
    sH[warp][lane] = h;
    __syncwarp();
    float o = 0.f;
#pragma unroll
    for (int k = 0; k < 32; k++) o = fmaf(sH[warp][k], sW[k * 32 + lane], o);
    g_xw[node * 32 + lane]  = o;
    g_acc[node * 32 + lane] = o * g_dinv2[node];
}

__global__ void k_node_xw(const float* __restrict__ bprev, const float* __restrict__ W,
                          int latOff, int n) {
    __shared__ float sW[1024];
    __shared__ float sH[8][32];
    int tid = threadIdx.x;
    for (int i = tid; i < 1024; i += 256) sW[i] = W[i];
    __syncthreads();
    int warp = tid >> 5, lane = tid & 31;
    int node = blockIdx.x * 8 + warp;
    if (node >= n) return;
    float h = tanhf(g_acc[node * 32 + lane] + bprev[lane]);
    g_lat[node * DLAT + latOff + lane] = h;
    sH[warp][lane] = h;
    __syncwarp();
    float o = 0.f;
#pragma unroll
    for (int k = 0; k < 32; k++) o = fmaf(sH[warp][k], sW[k * 32 + lane], o);
    g_xw[node * 32 + lane]  = o;  // safe: each element read-then-written by same thread
    g_acc[node * 32 + lane] = o * g_dinv2[node];
}

// layer 4: width-1 output
__global__ void k_node_xw4(const float* __restrict__ bg3, const float* __restrict__ Wg4, int n) {
    int tid = blockIdx.x * blockDim.x + threadIdx.x;
    int node = tid >> 5, lane = tid & 31;
    if (node >= n) return;
    float h = tanhf(g_acc[node * 32 + lane] + bg3[lane]);
    g_lat[node * DLAT + 64 + lane] = h;
    float p = h * Wg4[lane];
#pragma unroll
    for (int off = 16; off; off >>= 1) p += __shfl_down_sync(0xffffffffu, p, off);
    if (lane == 0) {
        g_xw4[node]  = p;
        g_acc4[node] = p * g_dinv2[node];
    }
}

// ---- edge scatter: acc[dst] += norm * xw[src]. 8 lanes per edge (float4 each)
//      so each warp gathers 4 full 128B rows coalesced. -----------------------

__global__ void k_edge_scatter32(const int* __restrict__ src, const int* __restrict__ dst, int e) {
    int tid = blockIdx.x * blockDim.x + threadIdx.x;
    int ed = tid >> 3;           // edge id
    int q  = tid & 7;            // float4 slot within 32-float row
    if (ed >= e) return;
    int s = src[ed], d = dst[ed];
    float w = g_norm[ed];
    float4 v = ((const float4*)(g_xw + (size_t)s * 32))[q];
    red_add_v4(((float4*)(g_acc + (size_t)d * 32)) + q, v.x * w, v.y * w, v.z * w, v.w * w);
}

__global__ void k_edge_scatter1(const int* __restrict__ src, const int* __restrict__ dst, int e) {
    int i = blockIdx.x * blockDim.x + threadIdx.x;
    if (i >= e) return;
    red_add_f32(&g_acc4[dst[i]], g_norm[i] * g_xw4[src[i]]);
}

// ---- per-graph head: sort-pool + conv/mlp stack. One block (128 thr) per graph.

__global__ void __launch_bounds__(128)
k_head(const float* __restrict__ bg4,
       const float* __restrict__ Wc1, const float* __restrict__ bc1,
       const float* __restrict__ Wc2, const float* __restrict__ bc2,
       const float* __restrict__ Wl1, const float* __restrict__ bl1,
       const float* __restrict__ Wl2, const float* __restrict__ bl2,
       float* __restrict__ out) {
    __shared__ float v[100];
    __shared__ int   topidx[30];
    __shared__ float top[30 * DLAT];
    __shared__ float y1[16 * 30];
    __shared__ float pmax[16 * 15];
    __shared__ float y2[352];
    __shared__ float fvec[128];
    __shared__ float sred[4];

    int g = blockIdx.x;
    int t = threadIdx.x;
    float b4 = bg4[0];

    if (t < 100) v[t] = tanhf(g_acc4[g * 100 + t] + b4);
    __syncthreads();

    // rank = count of strictly-larger + equal-with-smaller-index (stable desc sort)
    if (t < 100) {
        float vt = v[t];
        int r = 0;
#pragma unroll 4
        for (int m = 0; m < 100; m++) {
            float vm = v[m];
            r += (vm > vt) || (vm == vt && m < t);
        }
        if (r < 30) topidx[r] = t;
    }
    __syncthreads();

    // gather top-30 rows of the 97-dim latent
    for (int e = t; e < 30 * DLAT; e += 128) {
        int r = e / DLAT, d = e - DLAT * r;
        int nd = topidx[r];
        top[e] = (d < 96) ? g_lat[(size_t)(g * 100 + nd) * DLAT + d] : v[nd];
    }
    __syncthreads();

    // Conv1d(1,16,97,stride 97): y1[c][k] = relu(sum_d top[k][d]*Wc1[c][d] + bc1[c])
    for (int o = t; o < 16 * 30; o += 128) {
        int c = o / 30, k = o - 30 * c;
        const float* w  = Wc1 + c * DLAT;
        const float* tp = top + k * DLAT;
        float s = bc1[c];
        for (int d = 0; d < DLAT; d++) s = fmaf(tp[d], w[d], s);
        y1[c * 30 + k] = fmaxf(s, 0.f);
    }
    __syncthreads();

    // MaxPool1d(2,2): 30 -> 15
    for (int o = t; o < 16 * 15; o += 128) {
        int c = o / 15, k = o - 15 * c;
        pmax[o] = fmaxf(y1[c * 30 + 2 * k], y1[c * 30 + 2 * k + 1]);
    }
    __syncthreads();

    // Conv1d(16,32,5): y2[o][k] = relu(sum_{i,tt} p[i][k+tt]*Wc2[o][i][tt] + bc2[o])
    for (int o2 = t; o2 < 32 * 11; o2 += 128) {
        int o = o2 / 11, k = o2 - 11 * o;
        float s = bc2[o];
        for (int i = 0; i < 16; i++) {
            const float* wp = Wc2 + (o * 16 + i) * 5;
            const float* pp = pmax + i * 15 + k;
#pragma unroll
            for (int tt = 0; tt < 5; tt++) s = fmaf(pp[tt], wp[tt], s);
        }
        y2[o2] = fmaxf(s, 0.f);  // flatten index m = o*11 + k == o2
    }
    __syncthreads();

    // FC(352,128) + relu
    {
        float s = bl1[t];
        for (int m = 0; m < 352; m++) s = fmaf(y2[m], Wl1[m * 128 + t], s);
        fvec[t] = fmaxf(s, 0.f);
    }
    __syncthreads();

    // FC(128,1)
    float s = fvec[t] * Wl2[t];
#pragma unroll
    for (int off = 16; off; off >>= 1) s += __shfl_down_sync(0xffffffffu, s, off);
    if ((t & 31) == 0) sred[t >> 5] = s;
    __syncthreads();
    if (t == 0) out[g] = sred[0] + sred[1] + sred[2] + sred[3] + bl2[0];
}

// ---------------------------------------------------------------------------

extern "C" void kernel_launch(void* const* d_in, const int* in_sizes, int n_in,
                              void* d_out, int out_size) {
    const int*   z    = (const int*)d_in[0];
    const int*   eidx = (const int*)d_in[1];
    const float* ew   = (const float*)d_in[3];
    const float* zemb = (const float*)d_in[4];
    const float* Wg1 = (const float*)d_in[5];
    const float* bg1 = (const float*)d_in[6];
    const float* Wg2 = (const float*)d_in[7];
    const float* bg2 = (const float*)d_in[8];
    const float* Wg3 = (const float*)d_in[9];
    const float* bg3 = (const float*)d_in[10];
    const float* Wg4 = (const float*)d_in[11];
    const float* bg4 = (const float*)d_in[12];
    const float* Wc1 = (const float*)d_in[13];
    const float* bc1 = (const float*)d_in[14];
    const float* Wc2 = (const float*)d_in[15];
    const float* bc2 = (const float*)d_in[16];
    const float* Wl1 = (const float*)d_in[17];
    const float* bl1 = (const float*)d_in[18];
    const float* Wl2 = (const float*)d_in[19];
    const float* bl2 = (const float*)d_in[20];
    float* out = (float*)d_out;

    const int n = in_sizes[0];          // 100000
    const int e = in_sizes[3];          // 1600000
    const int* src = eidx;
    const int* dst = eidx + e;

    const int TB = 256;
    int gN   = (n + TB - 1) / TB;
    int gE   = (e + TB - 1) / TB;
    int gN8  = (n + 7) / 8;             // warp per node
    int gN32 = (n * 32 + TB - 1) / TB;  // warp per node, flat
    int gE8  = ((e * 8) + TB - 1) / TB; // 8 lanes per edge

    // normalization (layer-invariant)
    k_init_deg<<<gN, TB>>>(n);
    k_edge_deg<<<gE, TB>>>(dst, ew, e);
    k_dinv<<<gN, TB>>>(n);
    k_edge_norm<<<gE, TB>>>(src, dst, ew, e);

    // layer 1 (embedding input)
    k_node_emb<<<gN8, TB>>>(z, zemb, Wg1, n);
    k_edge_scatter32<<<gE8, TB>>>(src, dst, e);
    // layer 2 (applies tanh+bg1, stores lat[0:32])
    k_node_xw<<<gN8, TB>>>(bg1, Wg2, 0, n);
    k_edge_scatter32<<<gE8, TB>>>(src, dst, e);
    // layer 3 (applies tanh+bg2, stores lat[32:64])
    k_node_xw<<<gN8, TB>>>(bg2, Wg3, 32, n);
    k_edge_scatter32<<<gE8, TB>>>(src, dst, e);
    // layer 4 (applies tanh+bg3, stores lat[64:96]; width-1 projection)
    k_node_xw4<<<gN32, TB>>>(bg3, Wg4, n);
    k_edge_scatter1<<<gE, TB>>>(src, dst, e);

    // sort-pool + head (tanh+bg4 applied inside; lat[96] kept in smem)
    k_head<<<NG, 128>>>(bg4, Wc1, bc1, Wc2, bc2, Wl1, bl1, Wl2, bl2, out);
}

// round 3
// speedup vs baseline: 1.0477x; 1.0477x over previous
#include <cuda_runtime.h>
#include <math.h>

// ---------------------------------------------------------------------------
// DGCNN forward, CSR-gather formulation.
// N=100000 nodes, E=1600000 edges, 1000 graphs x 100 nodes, hid=32, DLAT=97.
// Pipeline per call:
//   zero -> countfill (padded CSR by dst, slot stride 64) -> dinv -> adjnorm
//   -> emb GEMM -> 2x fused(agg+tanh+lat+GEMM) -> fused(agg+tanh+lat+dot Wg4)
//   -> head (scalar agg + sortpool + convs + MLP)
// ---------------------------------------------------------------------------

#define NN 100000
#define EE 1600000
#define NG 1000
#define DLAT 97
#define SLOT 64   // padded CSR row stride (max degree; Poisson(16) tail ~1e-20)

__device__ int   g_cnt[NN];
__device__ float g_deg[NN];
__device__ float g_dinv[NN];
__device__ float g_dinv2[NN];
__device__ int2  g_adj[(size_t)NN * SLOT];   // (src, bits: ew then norm)
__device__ float g_xwA[NN * 32];
__device__ float g_xwB[NN * 32];
__device__ float g_lat[(size_t)NN * DLAT];
__device__ float g_xw4[NN];

__device__ __forceinline__ void red_add_f32(float* p, float v) {
    asm volatile("red.global.add.f32 [%0], %1;" :: "l"(p), "f"(v) : "memory");
}

// ---- CSR build --------------------------------------------------------------

__global__ void k_zero(int n) {
    int i = blockIdx.x * blockDim.x + threadIdx.x;
    if (i < n) { g_cnt[i] = 0; g_deg[i] = 1.0f; }  // deg starts at self-loop wt
}

__global__ void k_countfill(const int* __restrict__ src, const int* __restrict__ dst,
                            const float* __restrict__ ew, int e) {
    int i = blockIdx.x * blockDim.x + threadIdx.x;
    if (i >= e) return;
    int d = dst[i], s = src[i];
    float w = ew[i];
    red_add_f32(&g_deg[d], w);
    int pos = atomicAdd(&g_cnt[d], 1);
    if (pos < SLOT) g_adj[(size_t)d * SLOT + pos] = make_int2(s, __float_as_int(w));
}

__global__ void k_dinv(int n) {
    int i = blockIdx.x * blockDim.x + threadIdx.x;
    if (i < n) {
        float r = rsqrtf(g_deg[i]);
        g_dinv[i]  = r;
        g_dinv2[i] = r * r;
    }
}

// ew -> dinv[s]*ew*dinv[d], in place. Warp per node, lane per slot.
__global__ void k_adjnorm(int n) {
    int tid  = blockIdx.x * blockDim.x + threadIdx.x;
    int node = tid >> 5, lane = tid & 31;
    if (node >= n) return;
    int c = min(g_cnt[node], SLOT);
    float dd = g_dinv[node];
    int2* row = g_adj + (size_t)node * SLOT;
    for (int j = lane; j < c; j += 32) {
        int2 a = row[j];
        a.y = __float_as_int(g_dinv[a.x] * __int_as_float(a.y) * dd);
        row[j] = a;
    }
}

// ---- node GEMM from embedding: xwA = z_emb[z] @ Wg1 -------------------------

__global__ void k_emb(const int* __restrict__ z, const float* __restrict__ z_emb,
                      const float* __restrict__ W, int n) {
    __shared__ float sW[1024];
    int tid = threadIdx.x;
    for (int i = tid; i < 1024; i += 256) sW[i] = W[i];
    __syncthreads();
    int warp = tid >> 5, lane = tid & 31;
    int node = blockIdx.x * 8 + warp;
    if (node >= n) return;
    float h = z_emb[z[node] * 32 + lane];
    float o = 0.f;
#pragma unroll
    for (int k = 0; k < 32; k++)
        o = fmaf(__shfl_sync(0xffffffffu, h, k), sW[k * 32 + lane], o);
    g_xwA[node * 32 + lane] = o;
}

// ---- fused layer: acc = Â xwIn  ->  h = tanh(acc+b) -> lat slice,
//      xwOut = h @ W.  Warp per node; lane = channel. ------------------------

__device__ __forceinline__ float agg_node(const float* __restrict__ xwIn,
                                          int node, int lane) {
    float acc = xwIn[node * 32 + lane] * g_dinv2[node];
    int c = min(g_cnt[node], SLOT);
    const int2* row  = g_adj + (size_t)node * SLOT;
    const int4* row4 = (const int4*)row;          // 2 edges per int4
    int j = 0;
    for (; j + 4 <= c; j += 4) {
        int4 m0 = row4[(j >> 1)];
        int4 m1 = row4[(j >> 1) + 1];
        float v0 = xwIn[m0.x * 32 + lane];
        float v1 = xwIn[m0.z * 32 + lane];
        float v2 = xwIn[m1.x * 32 + lane];
        float v3 = xwIn[m1.z * 32 + lane];
        acc = fmaf(__int_as_float(m0.y), v0, acc);
        acc = fmaf(__int_as_float(m0.w), v1, acc);
        acc = fmaf(__int_as_float(m1.y), v2, acc);
        acc = fmaf(__int_as_float(m1.w), v3, acc);
    }
    for (; j < c; j++) {
        int2 a = row[j];
        acc = fmaf(__int_as_float(a.y), xwIn[a.x * 32 + lane], acc);
    }
    return acc;
}

__global__ void __launch_bounds__(256)
k_layer32(const float* __restrict__ bprev, const float* __restrict__ W,
          int latOff, const float* __restrict__ xwIn, float* __restrict__ xwOut, int n) {
    __shared__ float sW[1024];
    int tid = threadIdx.x;
    for (int i = tid; i < 1024; i += 256) sW[i] = W[i];
    __syncthreads();
    int warp = tid >> 5, lane = tid & 31;
    int node = blockIdx.x * 8 + warp;
    if (node >= n) return;
    float acc = agg_node(xwIn, node, lane);
    float h = tanhf(acc + bprev[lane]);
    g_lat[(size_t)node * DLAT + latOff + lane] = h;
    float o = 0.f;
#pragma unroll
    for (int k = 0; k < 32; k++)
        o = fmaf(__shfl_sync(0xffffffffu, h, k), sW[k * 32 + lane], o);
    xwOut[node * 32 + lane] = o;
}

// last GCN layer: project to scalar via Wg4
__global__ void __launch_bounds__(256)
k_layer_last(const float* __restrict__ bg3, const float* __restrict__ Wg4,
             const float* __restrict__ xwIn, int n) {
    int tid = blockIdx.x * blockDim.x + threadIdx.x;
    int node = tid >> 5, lane = tid & 31;
    if (node >= n) return;
    float acc = agg_node(xwIn, node, lane);
    float h = tanhf(acc + bg3[lane]);
    g_lat[(size_t)node * DLAT + 64 + lane] = h;
    float p = h * Wg4[lane];
#pragma unroll
    for (int off = 16; off; off >>= 1) p += __shfl_down_sync(0xffffffffu, p, off);
    if (lane == 0) g_xw4[node] = p;
}

// ---- per-graph head: scalar agg + sort-pool + conv/mlp. Block/graph. --------

__global__ void __launch_bounds__(128)
k_head(const float* __restrict__ bg4,
       const float* __restrict__ Wc1, const float* __restrict__ bc1,
       const float* __restrict__ Wc2, const float* __restrict__ bc2,
       const float* __restrict__ Wl1, const float* __restrict__ bl1,
       const float* __restrict__ Wl2, const float* __restrict__ bl2,
       float* __restrict__ out) {
    __shared__ float v[100];
    __shared__ int   topidx[30];
    __shared__ float top[30 * DLAT];
    __shared__ float y1[16 * 30];
    __shared__ float pmax[16 * 15];
    __shared__ float y2[352];
    __shared__ float fvec[128];
    __shared__ float sred[4];

    int g = blockIdx.x;
    int t = threadIdx.x;
    float b4 = bg4[0];

    // layer-4 scalar aggregation, thread per node
    if (t < 100) {
        int node = g * 100 + t;
        float acc = g_xw4[node] * g_dinv2[node];
        int c = min(g_cnt[node], SLOT);
        const int2* row  = g_adj + (size_t)node * SLOT;
        const int4* row4 = (const int4*)row;
        int j = 0;
        for (; j + 4 <= c; j += 4) {
            int4 m0 = row4[(j >> 1)];
            int4 m1 = row4[(j >> 1) + 1];
            float v0 = g_xw4[m0.x], v1 = g_xw4[m0.z];
            float v2 = g_xw4[m1.x], v3 = g_xw4[m1.z];
            acc = fmaf(__int_as_float(m0.y), v0, acc);
            acc = fmaf(__int_as_float(m0.w), v1, acc);
            acc = fmaf(__int_as_float(m1.y), v2, acc);
            acc = fmaf(__int_as_float(m1.w), v3, acc);
        }
        for (; j < c; j++) {
            int2 a = row[j];
            acc = fmaf(__int_as_float(a.y), g_xw4[a.x], acc);
        }
        v[t] = tanhf(acc + b4);
    }
    __syncthreads();

    // stable descending rank select (ties -> lower index first)
    if (t < 100) {
        float vt = v[t];
        int r = 0;
#pragma unroll 4
        for (int m = 0; m < 100; m++) {
            float vm = v[m];
            r += (vm > vt) || (vm == vt && m < t);
        }
        if (r < 30) topidx[r] = t;
    }
    __syncthreads();

    // gather top-30 latent rows
    for (int e = t; e < 30 * DLAT; e += 128) {
        int r = e / DLAT, d = e - DLAT * r;
        int nd = topidx[r];
        top[e] = (d < 96) ? g_lat[(size_t)(g * 100 + nd) * DLAT + d] : v[nd];
    }
    __syncthreads();

    // Conv1d(1,16,97,stride 97)
    for (int o = t; o < 16 * 30; o += 128) {
        int c = o / 30, k = o - 30 * c;
        const float* w  = Wc1 + c * DLAT;
        const float* tp = top + k * DLAT;
        float s = bc1[c];
        for (int d = 0; d < DLAT; d++) s = fmaf(tp[d], w[d], s);
        y1[c * 30 + k] = fmaxf(s, 0.f);
    }
    __syncthreads();

    // MaxPool1d(2,2)
    for (int o = t; o < 16 * 15; o += 128) {
        int c = o / 15, k = o - 15 * c;
        pmax[o] = fmaxf(y1[c * 30 + 2 * k], y1[c * 30 + 2 * k + 1]);
    }
    __syncthreads();

    // Conv1d(16,32,5)
    for (int o2 = t; o2 < 32 * 11; o2 += 128) {
        int o = o2 / 11, k = o2 - 11 * o;
        float s = bc2[o];
        for (int i = 0; i < 16; i++) {
            const float* wp = Wc2 + (o * 16 + i) * 5;
            const float* pp = pmax + i * 15 + k;
#pragma unroll
            for (int tt = 0; tt < 5; tt++) s = fmaf(pp[tt], wp[tt], s);
        }
        y2[o2] = fmaxf(s, 0.f);
    }
    __syncthreads();

    // FC(352,128) + relu
    {
        float s = bl1[t];
        for (int m = 0; m < 352; m++) s = fmaf(y2[m], Wl1[m * 128 + t], s);
        fvec[t] = fmaxf(s, 0.f);
    }
    __syncthreads();

    // FC(128,1)
    float s = fvec[t] * Wl2[t];
#pragma unroll
    for (int off = 16; off; off >>= 1) s += __shfl_down_sync(0xffffffffu, s, off);
    if ((t & 31) == 0) sred[t >> 5] = s;
    __syncthreads();
    if (t == 0) out[g] = sred[0] + sred[1] + sred[2] + sred[3] + bl2[0];
}

// ---------------------------------------------------------------------------

extern "C" void kernel_launch(void* const* d_in, const int* in_sizes, int n_in,
                              void* d_out, int out_size) {
    const int*   z    = (const int*)d_in[0];
    const int*   eidx = (const int*)d_in[1];
    const float* ew   = (const float*)d_in[3];
    const float* zemb = (const float*)d_in[4];
    const float* Wg1 = (const float*)d_in[5];
    const float* bg1 = (const float*)d_in[6];
    const float* Wg2 = (const float*)d_in[7];
    const float* bg2 = (const float*)d_in[8];
    const float* Wg3 = (const float*)d_in[9];
    const float* bg3 = (const float*)d_in[10];
    const float* Wg4 = (const float*)d_in[11];
    const float* bg4 = (const float*)d_in[12];
    const float* Wc1 = (const float*)d_in[13];
    const float* bc1 = (const float*)d_in[14];
    const float* Wc2 = (const float*)d_in[15];
    const float* bc2 = (const float*)d_in[16];
    const float* Wl1 = (const float*)d_in[17];
    const float* bl1 = (const float*)d_in[18];
    const float* Wl2 = (const float*)d_in[19];
    const float* bl2 = (const float*)d_in[20];
    float* out = (float*)d_out;

    const int n = in_sizes[0];          // 100000
    const int e = in_sizes[3];          // 1600000
    const int* src = eidx;
    const int* dst = eidx + e;

    const int TB = 256;
    int gN   = (n + TB - 1) / TB;
    int gE   = (e + TB - 1) / TB;
    int gN8  = (n + 7) / 8;             // warp per node
    int gN32 = (n * 32 + TB - 1) / TB;  // warp per node, flat grid

    float *xwA, *xwB;
    cudaGetSymbolAddress((void**)&xwA, g_xwA);
    cudaGetSymbolAddress((void**)&xwB, g_xwB);

    // build padded CSR + normalization (layer-invariant)
    k_zero<<<gN, TB>>>(n);
    k_countfill<<<gE, TB>>>(src, dst, ew, e);
    k_dinv<<<gN, TB>>>(n);
    k_adjnorm<<<gN32, TB>>>(n);

    // GCN stack, fused per layer
    k_emb<<<gN8, TB>>>(z, zemb, Wg1, n);                       // xwA = emb @ Wg1
    k_layer32<<<gN8, TB>>>(bg1, Wg2, 0,  xwA, xwB, n);         // h1 -> lat[0:32],  xwB = h1@Wg2
    k_layer32<<<gN8, TB>>>(bg2, Wg3, 32, xwB, xwA, n);         // h2 -> lat[32:64], xwA = h2@Wg3
    k_layer_last<<<gN32, TB>>>(bg3, Wg4, xwA, n);              // h3 -> lat[64:96], xw4 = h3@Wg4

    // scalar aggregation + sort-pool + head
    k_head<<<NG, 128>>>(bg4, Wc1, bc1, Wc2, bc2, Wl1, bl1, Wl2, bl2, out);
}

// round 4
// speedup vs baseline: 1.1076x; 1.0571x over previous
#include <cuda_runtime.h>
#include <math.h>

// ---------------------------------------------------------------------------
// DGCNN forward, CSR-gather with pre-scaled features.
//   xws[v] = (h@W) * dinv[v]   =>   gcn_out[d] = dinv[d]*(sum_e ew*xws[src] + xws[d])
// so the adjacency stores RAW edge weights (no normalization pass), and rows
// are padded to a multiple of 8 with zero-weight edges (no scalar tail).
// N=100000, E=1600000, 1000 graphs x 100 nodes, hid=32, DLAT=97.
// ---------------------------------------------------------------------------

#define NN 100000
#define EE 1600000
#define NG 1000
#define DLAT 97
#define SLOT 64   // padded CSR row stride (Poisson(16) tail beyond 64 ~1e-20)

__device__ int   g_cnt[NN];
__device__ float g_dinv[NN];
__device__ int2  g_adj[(size_t)NN * SLOT];   // (src, ew bits)
__device__ float g_xwA[NN * 32];             // pre-scaled features (xws)
__device__ float g_xwB[NN * 32];
__device__ float g_lat[(size_t)NN * DLAT];
__device__ float g_xw4[NN];                  // pre-scaled scalar features

// ---- CSR build --------------------------------------------------------------

__global__ void k_zero(int n) {
    int i = blockIdx.x * blockDim.x + threadIdx.x;
    if (i < n) g_cnt[i] = 0;
}

__global__ void k_fill(const int* __restrict__ src, const int* __restrict__ dst,
                       const float* __restrict__ ew, int e) {
    int i = blockIdx.x * blockDim.x + threadIdx.x;
    if (i >= e) return;
    int d = dst[i];
    int pos = atomicAdd(&g_cnt[d], 1);
    if (pos < SLOT) g_adj[(size_t)d * SLOT + pos] = make_int2(src[i], __float_as_int(ew[i]));
}

// warp per node: deg = 1 + sum(row ew); dinv = rsqrt(deg); pad row to mult of 8.
__global__ void k_degdinv(int n) {
    int tid  = blockIdx.x * blockDim.x + threadIdx.x;
    int node = tid >> 5, lane = tid & 31;
    if (node >= n) return;
    int c = min(g_cnt[node], SLOT);
    int2* row = g_adj + (size_t)node * SLOT;
    float w = 0.f;
    if (lane < c)      w += __int_as_float(row[lane].y);
    if (lane + 32 < c) w += __int_as_float(row[lane + 32].y);
#pragma unroll
    for (int off = 16; off; off >>= 1) w += __shfl_xor_sync(0xffffffffu, w, off);
    int cpad = (c + 7) & ~7;
    if (c + lane < cpad) row[c + lane] = make_int2(0, 0);   // zero-weight dummy
    if (lane == 0) {
        g_dinv[node] = rsqrtf(1.0f + w);
        g_cnt[node]  = cpad;
    }
}

// ---- embedding layer: xwA = (z_emb[z] @ Wg1) * dinv ------------------------

__global__ void k_emb(const int* __restrict__ z, const float* __restrict__ z_emb,
                      const float* __restrict__ W, int n) {
    __shared__ float sW[1024];
    int tid = threadIdx.x;
    for (int i = tid; i < 1024; i += 256) sW[i] = W[i];
    __syncthreads();
    int warp = tid >> 5, lane = tid & 31;
    int node = blockIdx.x * 8 + warp;
    if (node >= n) return;
    float h = z_emb[z[node] * 32 + lane];
    float o = 0.f;
#pragma unroll
    for (int k = 0; k < 32; k++)
        o = fmaf(__shfl_sync(0xffffffffu, h, k), sW[k * 32 + lane], o);
    g_xwA[node * 32 + lane] = o * g_dinv[node];
}

// ---- aggregation: acc = sum ew*xws[src] + xws[self], 8 edges in flight ------

__device__ __forceinline__ float agg8(const float* __restrict__ xwIn,
                                      int node, int lane, int c) {
    float acc = xwIn[node * 32 + lane];
    const int4* row4 = (const int4*)(g_adj + (size_t)node * SLOT);
    for (int j = 0; j < c; j += 8) {
        int4 m0 = row4[(j >> 1) + 0];
        int4 m1 = row4[(j >> 1) + 1];
        int4 m2 = row4[(j >> 1) + 2];
        int4 m3 = row4[(j >> 1) + 3];
        float v0 = xwIn[m0.x * 32 + lane];
        float v1 = xwIn[m0.z * 32 + lane];
        float v2 = xwIn[m1.x * 32 + lane];
        float v3 = xwIn[m1.z * 32 + lane];
        float v4 = xwIn[m2.x * 32 + lane];
        float v5 = xwIn[m2.z * 32 + lane];
        float v6 = xwIn[m3.x * 32 + lane];
        float v7 = xwIn[m3.z * 32 + lane];
        acc = fmaf(__int_as_float(m0.y), v0, acc);
        acc = fmaf(__int_as_float(m0.w), v1, acc);
        acc = fmaf(__int_as_float(m1.y), v2, acc);
        acc = fmaf(__int_as_float(m1.w), v3, acc);
        acc = fmaf(__int_as_float(m2.y), v4, acc);
        acc = fmaf(__int_as_float(m2.w), v5, acc);
        acc = fmaf(__int_as_float(m3.y), v6, acc);
        acc = fmaf(__int_as_float(m3.w), v7, acc);
    }
    return acc;
}

// ---- fused GCN layer: agg -> tanh -> lat slice -> GEMM -> prescale ----------

__global__ void __launch_bounds__(256)
k_layer32(const float* __restrict__ bprev, const float* __restrict__ W,
          int latOff, const float* __restrict__ xwIn, float* __restrict__ xwOut, int n) {
    __shared__ float sW[1024];
    int tid = threadIdx.x;
    for (int i = tid; i < 1024; i += 256) sW[i] = W[i];
    __syncthreads();
    int warp = tid >> 5, lane = tid & 31;
    int node = blockIdx.x * 8 + warp;
    if (node >= n) return;
    float dv = g_dinv[node];
    int   c  = g_cnt[node];
    float acc = agg8(xwIn, node, lane, c);
    float h = tanhf(fmaf(acc, dv, bprev[lane]));
    g_lat[(size_t)node * DLAT + latOff + lane] = h;
    float o = 0.f;
#pragma unroll
    for (int k = 0; k < 32; k++)
        o = fmaf(__shfl_sync(0xffffffffu, h, k), sW[k * 32 + lane], o);
    xwOut[node * 32 + lane] = o * dv;
}

// last GCN layer: project to scalar via Wg4 (pre-scaled output)
__global__ void __launch_bounds__(256)
k_layer_last(const float* __restrict__ bg3, const float* __restrict__ Wg4,
             const float* __restrict__ xwIn, int n) {
    int tid = blockIdx.x * blockDim.x + threadIdx.x;
    int node = tid >> 5, lane = tid & 31;
    if (node >= n) return;
    float dv = g_dinv[node];
    int   c  = g_cnt[node];
    float acc = agg8(xwIn, node, lane, c);
    float h = tanhf(fmaf(acc, dv, bg3[lane]));
    g_lat[(size_t)node * DLAT + 64 + lane] = h;
    float p = h * Wg4[lane];
#pragma unroll
    for (int off = 16; off; off >>= 1) p += __shfl_down_sync(0xffffffffu, p, off);
    if (lane == 0) g_xw4[node] = p * dv;
}

// ---- per-graph head: scalar agg + sort-pool + conv/mlp. Block/graph. --------

__global__ void __launch_bounds__(128)
k_head(const float* __restrict__ bg4,
       const float* __restrict__ Wc1, const float* __restrict__ bc1,
       const float* __restrict__ Wc2, const float* __restrict__ bc2,
       const float* __restrict__ Wl1, const float* __restrict__ bl1,
       const float* __restrict__ Wl2, const float* __restrict__ bl2,
       float* __restrict__ out) {
    __shared__ float v[100];
    __shared__ int   topidx[30];
    __shared__ float top[30 * DLAT];
    __shared__ float y1[16 * 30];
    __shared__ float pmax[16 * 15];
    __shared__ float y2[352];
    __shared__ float fvec[128];
    __shared__ float sred[4];

    int g = blockIdx.x;
    int t = threadIdx.x;
    float b4 = bg4[0];

    // layer-4 scalar aggregation, thread per node (rows padded, mult of 8)
    if (t < 100) {
        int node = g * 100 + t;
        float acc = g_xw4[node];
        int c = g_cnt[node];
        const int4* row4 = (const int4*)(g_adj + (size_t)node * SLOT);
        for (int j = 0; j < c; j += 8) {
            int4 m0 = row4[(j >> 1) + 0];
            int4 m1 = row4[(j >> 1) + 1];
            int4 m2 = row4[(j >> 1) + 2];
            int4 m3 = row4[(j >> 1) + 3];
            float v0 = g_xw4[m0.x], v1 = g_xw4[m0.z];
            float v2 = g_xw4[m1.x], v3 = g_xw4[m1.z];
            float v4 = g_xw4[m2.x], v5 = g_xw4[m2.z];
            float v6 = g_xw4[m3.x], v7 = g_xw4[m3.z];
            acc = fmaf(__int_as_float(m0.y), v0, acc);
            acc = fmaf(__int_as_float(m0.w), v1, acc);
            acc = fmaf(__int_as_float(m1.y), v2, acc);
            acc = fmaf(__int_as_float(m1.w), v3, acc);
            acc = fmaf(__int_as_float(m2.y), v4, acc);
            acc = fmaf(__int_as_float(m2.w), v5, acc);
            acc = fmaf(__int_as_float(m3.y), v6, acc);
            acc = fmaf(__int_as_float(m3.w), v7, acc);
        }
        v[t] = tanhf(fmaf(acc, g_dinv[node], b4));
    }
    __syncthreads();

    // stable descending rank select (ties -> lower index first)
    if (t < 100) {
        float vt = v[t];
        int r = 0;
#pragma unroll 4
        for (int m = 0; m < 100; m++) {
            float vm = v[m];
            r += (vm > vt) || (vm == vt && m < t);
        }
        if (r < 30) topidx[r] = t;
    }
    __syncthreads();

    // gather top-30 latent rows
    for (int e = t; e < 30 * DLAT; e += 128) {
        int r = e / DLAT, d = e - DLAT * r;
        int nd = topidx[r];
        top[e] = (d < 96) ? g_lat[(size_t)(g * 100 + nd) * DLAT + d] : v[nd];
    }
    __syncthreads();

    // Conv1d(1,16,97,stride 97)
    for (int o = t; o < 16 * 30; o += 128) {
        int c = o / 30, k = o - 30 * c;
        const float* w  = Wc1 + c * DLAT;
        const float* tp = top + k * DLAT;
        float s = bc1[c];
        for (int d = 0; d < DLAT; d++) s = fmaf(tp[d], w[d], s);
        y1[c * 30 + k] = fmaxf(s, 0.f);
    }
    __syncthreads();

    // MaxPool1d(2,2)
    for (int o = t; o < 16 * 15; o += 128) {
        int c = o / 15, k = o - 15 * c;
        pmax[o] = fmaxf(y1[c * 30 + 2 * k], y1[c * 30 + 2 * k + 1]);
    }
    __syncthreads();

    // Conv1d(16,32,5)
    for (int o2 = t; o2 < 32 * 11; o2 += 128) {
        int o = o2 / 11, k = o2 - 11 * o;
        float s = bc2[o];
        for (int i = 0; i < 16; i++) {
            const float* wp = Wc2 + (o * 16 + i) * 5;
            const float* pp = pmax + i * 15 + k;
#pragma unroll
            for (int tt = 0; tt < 5; tt++) s = fmaf(pp[tt], wp[tt], s);
        }
        y2[o2] = fmaxf(s, 0.f);
    }
    __syncthreads();

    // FC(352,128) + relu
    {
        float s = bl1[t];
        for (int m = 0; m < 352; m++) s = fmaf(y2[m], Wl1[m * 128 + t], s);
        fvec[t] = fmaxf(s, 0.f);
    }
    __syncthreads();

    // FC(128,1)
    float s = fvec[t] * Wl2[t];
#pragma unroll
    for (int off = 16; off; off >>= 1) s += __shfl_down_sync(0xffffffffu, s, off);
    if ((t & 31) == 0) sred[t >> 5] = s;
    __syncthreads();
    if (t == 0) out[g] = sred[0] + sred[1] + sred[2] + sred[3] + bl2[0];
}

// ---------------------------------------------------------------------------

extern "C" void kernel_launch(void* const* d_in, const int* in_sizes, int n_in,
                              void* d_out, int out_size) {
    const int*   z    = (const int*)d_in[0];
    const int*   eidx = (const int*)d_in[1];
    const float* ew   = (const float*)d_in[3];
    const float* zemb = (const float*)d_in[4];
    const float* Wg1 = (const float*)d_in[5];
    const float* bg1 = (const float*)d_in[6];
    const float* Wg2 = (const float*)d_in[7];
    const float* bg2 = (const float*)d_in[8];
    const float* Wg3 = (const float*)d_in[9];
    const float* bg3 = (const float*)d_in[10];
    const float* Wg4 = (const float*)d_in[11];
    const float* bg4 = (const float*)d_in[12];
    const float* Wc1 = (const float*)d_in[13];
    const float* bc1 = (const float*)d_in[14];
    const float* Wc2 = (const float*)d_in[15];
    const float* bc2 = (const float*)d_in[16];
    const float* Wl1 = (const float*)d_in[17];
    const float* bl1 = (const float*)d_in[18];
    const float* Wl2 = (const float*)d_in[19];
    const float* bl2 = (const float*)d_in[20];
    float* out = (float*)d_out;

    const int n = in_sizes[0];          // 100000
    const int e = in_sizes[3];          // 1600000
    const int* src = eidx;
    const int* dst = eidx + e;

    const int TB = 256;
    int gN   = (n + TB - 1) / TB;
    int gE   = (e + TB - 1) / TB;
    int gN8  = (n + 7) / 8;             // warp per node (8 warps/block)
    int gN32 = (n * 32 + TB - 1) / TB;  // warp per node, flat grid

    float *xwA, *xwB;
    cudaGetSymbolAddress((void**)&xwA, g_xwA);
    cudaGetSymbolAddress((void**)&xwB, g_xwB);

    // build padded CSR + dinv (raw edge weights; no normalization pass)
    k_zero<<<gN, TB>>>(n);
    k_fill<<<gE, TB>>>(src, dst, ew, e);
    k_degdinv<<<gN32, TB>>>(n);

    // GCN stack, fused per layer (all features pre-scaled by dinv)
    k_emb<<<gN8, TB>>>(z, zemb, Wg1, n);
    k_layer32<<<gN8, TB>>>(bg1, Wg2, 0,  xwA, xwB, n);
    k_layer32<<<gN8, TB>>>(bg2, Wg3, 32, xwB, xwA, n);
    k_layer_last<<<gN32, TB>>>(bg3, Wg4, xwA, n);

    // scalar aggregation + sort-pool + head
    k_head<<<NG, 128>>>(bg4, Wc1, bc1, Wc2, bc2, Wl1, bl1, Wl2, bl2, out);
}